// round 5
// baseline (speedup 1.0000x reference)
#include <cuda_runtime.h>
#include <cstdint>

#define NUM_INPUT_NODES  524288
#define NUM_LAYER_NODES  262144
#define BATCH            128
#define NPI              2          // nodes per pipeline stage
#define THREADS          256
#define BLOCKS           1216       // ~8 blocks x 152 SMs; grid-stride persistent

// Persistent warps, 2-stage software pipeline. Each chunk = 2 output rows;
// lane l covers float4 slot l of each 128-float row. Next chunk's index +
// gather loads are issued BEFORE the current chunk's stores, so every warp
// keeps loads in flight continuously (no load->store->exit dead time).
// Stores are evict-first (.cs): output is write-once; don't evict the
// duplicate-heavy gather rows from L2.
__global__ void __launch_bounds__(THREADS)
prod_layer_kernel(const float* __restrict__ node_mars,
                  const float* __restrict__ element_mars,
                  const int* __restrict__ nids,
                  const int* __restrict__ cids,
                  float* __restrict__ out)
{
    const unsigned lane   = threadIdx.x & 31;
    const unsigned gwarp  = (blockIdx.x * blockDim.x + threadIdx.x) >> 5;
    const unsigned nwarps = (gridDim.x * blockDim.x) >> 5;

    const float4* nm = reinterpret_cast<const float4*>(node_mars);
    float4*       o  = reinterpret_cast<float4*>(out);
    const unsigned F4 = BATCH / 4;   // 32 float4 per row

    if (gwarp == 0) {
        // Reserved row 0: pass through element_mars[0, :] (d_out poisoned).
        const float4* src = reinterpret_cast<const float4*>(element_mars);
        o[lane] = src[lane];
    }

    const unsigned nchunks = NUM_LAYER_NODES / NPI;   // 131072
    unsigned c = gwarp;
    if (c >= nchunks) return;

    // ---- stage A: prime the pipeline ----
    int2 nA = __ldg(reinterpret_cast<const int2*>(&nids[NPI * c]));
    int4 cA = __ldg(reinterpret_cast<const int4*>(&cids[2 * NPI * c]));
    float4 a0 = __ldg(&nm[(long long)cA.x * F4 + lane]);
    float4 b0 = __ldg(&nm[(long long)cA.y * F4 + lane]);
    float4 a1 = __ldg(&nm[(long long)cA.z * F4 + lane]);
    float4 b1 = __ldg(&nm[(long long)cA.w * F4 + lane]);

    for (;;) {
        const unsigned nxt = c + nwarps;
        const bool have = (nxt < nchunks);

        // ---- stage B: issue next chunk's loads before current stores ----
        int2 nB;  int4 cB;
        float4 a0n, b0n, a1n, b1n;
        if (have) {
            nB  = __ldg(reinterpret_cast<const int2*>(&nids[NPI * nxt]));
            cB  = __ldg(reinterpret_cast<const int4*>(&cids[2 * NPI * nxt]));
            a0n = __ldg(&nm[(long long)cB.x * F4 + lane]);
            b0n = __ldg(&nm[(long long)cB.y * F4 + lane]);
            a1n = __ldg(&nm[(long long)cB.z * F4 + lane]);
            b1n = __ldg(&nm[(long long)cB.w * F4 + lane]);
        }

        // ---- drain stage A ----
        float4 r0 = make_float4(a0.x + b0.x, a0.y + b0.y,
                                a0.z + b0.z, a0.w + b0.w);
        __stcs(&o[(long long)nA.x * F4 + lane], r0);
        float4 r1 = make_float4(a1.x + b1.x, a1.y + b1.y,
                                a1.z + b1.z, a1.w + b1.w);
        __stcs(&o[(long long)nA.y * F4 + lane], r1);

        if (!have) break;

        // rotate B -> A
        nA = nB;  cA = cB;
        a0 = a0n; b0 = b0n; a1 = a1n; b1 = b1n;
        c = nxt;
    }
}

extern "C" void kernel_launch(void* const* d_in, const int* in_sizes, int n_in,
                              void* d_out, int out_size)
{
    const float* node_mars    = (const float*)d_in[0];
    const float* element_mars = (const float*)d_in[1];
    const int*   nids         = (const int*)d_in[2];
    const int*   cids         = (const int*)d_in[3];
    float*       out          = (float*)d_out;

    prod_layer_kernel<<<BLOCKS, THREADS>>>(node_mars, element_mars, nids, cids, out);
}

// round 6
// speedup vs baseline: 1.0204x; 1.0204x over previous
#include <cuda_runtime.h>
#include <cstdint>

#define NUM_INPUT_NODES  524288
#define NUM_LAYER_NODES  262144
#define BATCH            128
#define NODES_PER_WARP   4

// R3 shape (best measured): one-shot, one warp per 4 consecutive output rows,
// all 8 gather loads issued before any store. Change vs R3: stores are
// write-through (__stwt) so the 128 MiB write stream does NOT allocate in L2,
// leaving the full LTS for duplicate-heavy node_mars gather rows.
__global__ void __launch_bounds__(256)
prod_layer_kernel(const float* __restrict__ node_mars,
                  const float* __restrict__ element_mars,
                  const int* __restrict__ nids,
                  const int* __restrict__ cids,
                  float* __restrict__ out)
{
    const unsigned gwarp = (blockIdx.x * blockDim.x + threadIdx.x) >> 5;
    const unsigned lane  = threadIdx.x & 31;
    const unsigned base  = gwarp * NODES_PER_WARP;

    if (base >= NUM_LAYER_NODES) {
        if (base == NUM_LAYER_NODES) {
            // Reserved row 0: pass through element_mars[0, :] (d_out poisoned).
            const float4* src = reinterpret_cast<const float4*>(element_mars);
            float4* dst = reinterpret_cast<float4*>(out);
            dst[lane] = src[lane];
        }
        return;
    }

    // Vector-load indices: 4 nids (int4), 8 cids (2x int4); 16B-aligned.
    const int4 n4  = __ldg(reinterpret_cast<const int4*>(&nids[base]));
    const int4 c01 = __ldg(reinterpret_cast<const int4*>(&cids[2 * base]));
    const int4 c23 = __ldg(reinterpret_cast<const int4*>(&cids[2 * base + 4]));

    const float4* nm = reinterpret_cast<const float4*>(node_mars);
    const unsigned F4 = BATCH / 4;   // 32 float4 per row

    // Issue all 8 gather loads up front (independent -> 8 outstanding).
    float4 a0 = __ldg(&nm[(long long)c01.x * F4 + lane]);
    float4 b0 = __ldg(&nm[(long long)c01.y * F4 + lane]);
    float4 a1 = __ldg(&nm[(long long)c01.z * F4 + lane]);
    float4 b1 = __ldg(&nm[(long long)c01.w * F4 + lane]);
    float4 a2 = __ldg(&nm[(long long)c23.x * F4 + lane]);
    float4 b2 = __ldg(&nm[(long long)c23.y * F4 + lane]);
    float4 a3 = __ldg(&nm[(long long)c23.z * F4 + lane]);
    float4 b3 = __ldg(&nm[(long long)c23.w * F4 + lane]);

    float4* o = reinterpret_cast<float4*>(out);

    float4 r0 = make_float4(a0.x + b0.x, a0.y + b0.y, a0.z + b0.z, a0.w + b0.w);
    __stwt(&o[(long long)n4.x * F4 + lane], r0);
    float4 r1 = make_float4(a1.x + b1.x, a1.y + b1.y, a1.z + b1.z, a1.w + b1.w);
    __stwt(&o[(long long)n4.y * F4 + lane], r1);
    float4 r2 = make_float4(a2.x + b2.x, a2.y + b2.y, a2.z + b2.z, a2.w + b2.w);
    __stwt(&o[(long long)n4.z * F4 + lane], r2);
    float4 r3 = make_float4(a3.x + b3.x, a3.y + b3.y, a3.z + b3.z, a3.w + b3.w);
    __stwt(&o[(long long)n4.w * F4 + lane], r3);
}

extern "C" void kernel_launch(void* const* d_in, const int* in_sizes, int n_in,
                              void* d_out, int out_size)
{
    const float* node_mars    = (const float*)d_in[0];
    const float* element_mars = (const float*)d_in[1];
    const int*   nids         = (const int*)d_in[2];
    const int*   cids         = (const int*)d_in[3];
    float*       out          = (float*)d_out;

    // 262144/4 = 65536 work warps + 1 warp for reserved row 0.
    const unsigned total_warps   = NUM_LAYER_NODES / NODES_PER_WARP + 1;
    const unsigned threads       = 256;               // 8 warps/block
    const unsigned warps_per_blk = threads / 32;
    const unsigned blocks = (total_warps + warps_per_blk - 1) / warps_per_blk;

    prod_layer_kernel<<<blocks, threads>>>(node_mars, element_mars, nids, cids, out);
}

// round 7
// speedup vs baseline: 1.0452x; 1.0242x over previous
#include <cuda_runtime.h>
#include <cstdint>

#define NUM_INPUT_NODES  524288
#define NUM_LAYER_NODES  262144
#define BATCH            128
#define NODES_PER_WARP   4

// FINAL (lock-in of best measured variant, R3):
// One warp handles 4 consecutive output rows; lane l covers float4 slot l of
// each 128-float row. All 8 gather loads are issued before any store to
// maximize per-warp memory-level parallelism. Stores use evict-first (.cs)
// since the output is write-once and must not displace the duplicate-heavy
// node_mars gather rows from L2.
//
// Measured: kernel 51.3us, DRAM 76%, HBM 6.0TB/s. Sweeps over MLP (8 vs 16),
// occupancy, persistent-pipeline, and store policy (.cs/.wt) all pinned at
// ~6.0-6.1TB/s => empirical HBM ceiling for mixed random-read+stream-write;
// traffic is within ~7% of the 296MB floor (165MB unique gather reads +
// 128MB writes + 3MB indices).
__global__ void __launch_bounds__(256)
prod_layer_kernel(const float* __restrict__ node_mars,
                  const float* __restrict__ element_mars,
                  const int* __restrict__ nids,
                  const int* __restrict__ cids,
                  float* __restrict__ out)
{
    const unsigned gwarp = (blockIdx.x * blockDim.x + threadIdx.x) >> 5;
    const unsigned lane  = threadIdx.x & 31;
    const unsigned base  = gwarp * NODES_PER_WARP;

    if (base >= NUM_LAYER_NODES) {
        if (base == NUM_LAYER_NODES) {
            // Reserved row 0: pass through element_mars[0, :] (d_out poisoned).
            const float4* src = reinterpret_cast<const float4*>(element_mars);
            float4* dst = reinterpret_cast<float4*>(out);
            dst[lane] = src[lane];
        }
        return;
    }

    // Vector-load indices: 4 nids (int4), 8 cids (2x int4); 16B-aligned.
    const int4 n4  = __ldg(reinterpret_cast<const int4*>(&nids[base]));
    const int4 c01 = __ldg(reinterpret_cast<const int4*>(&cids[2 * base]));
    const int4 c23 = __ldg(reinterpret_cast<const int4*>(&cids[2 * base + 4]));

    const float4* nm = reinterpret_cast<const float4*>(node_mars);
    const unsigned F4 = BATCH / 4;   // 32 float4 per row

    // Issue all 8 gather loads up front (independent -> 8 outstanding).
    float4 a0 = __ldg(&nm[(long long)c01.x * F4 + lane]);
    float4 b0 = __ldg(&nm[(long long)c01.y * F4 + lane]);
    float4 a1 = __ldg(&nm[(long long)c01.z * F4 + lane]);
    float4 b1 = __ldg(&nm[(long long)c01.w * F4 + lane]);
    float4 a2 = __ldg(&nm[(long long)c23.x * F4 + lane]);
    float4 b2 = __ldg(&nm[(long long)c23.y * F4 + lane]);
    float4 a3 = __ldg(&nm[(long long)c23.z * F4 + lane]);
    float4 b3 = __ldg(&nm[(long long)c23.w * F4 + lane]);

    float4* o = reinterpret_cast<float4*>(out);

    float4 r0 = make_float4(a0.x + b0.x, a0.y + b0.y, a0.z + b0.z, a0.w + b0.w);
    __stcs(&o[(long long)n4.x * F4 + lane], r0);
    float4 r1 = make_float4(a1.x + b1.x, a1.y + b1.y, a1.z + b1.z, a1.w + b1.w);
    __stcs(&o[(long long)n4.y * F4 + lane], r1);
    float4 r2 = make_float4(a2.x + b2.x, a2.y + b2.y, a2.z + b2.z, a2.w + b2.w);
    __stcs(&o[(long long)n4.z * F4 + lane], r2);
    float4 r3 = make_float4(a3.x + b3.x, a3.y + b3.y, a3.z + b3.z, a3.w + b3.w);
    __stcs(&o[(long long)n4.w * F4 + lane], r3);
}

extern "C" void kernel_launch(void* const* d_in, const int* in_sizes, int n_in,
                              void* d_out, int out_size)
{
    const float* node_mars    = (const float*)d_in[0];
    const float* element_mars = (const float*)d_in[1];
    const int*   nids         = (const int*)d_in[2];
    const int*   cids         = (const int*)d_in[3];
    float*       out          = (float*)d_out;

    // 262144/4 = 65536 work warps + 1 warp for reserved row 0.
    const unsigned total_warps   = NUM_LAYER_NODES / NODES_PER_WARP + 1;
    const unsigned threads       = 256;               // 8 warps/block
    const unsigned warps_per_blk = threads / 32;
    const unsigned blocks = (total_warps + warps_per_blk - 1) / warps_per_blk;

    prod_layer_kernel<<<blocks, threads>>>(node_mars, element_mars, nids, cids, out);
}

// round 9
// speedup vs baseline: 1.0498x; 1.0044x over previous
#include <cuda_runtime.h>
#include <cstdint>

#define NUM_LAYER_NODES  262144
#define BATCH            128
#define NODES_PER_WARP   4

// 256-bit gather loads with L2::evict_last (only legal width for that hint on
// sm_103a). For each node, lanes 0-15 load child0's 512B row (32B/lane) and
// lanes 16-31 load child1's row in ONE v8.b32 instruction. shfl.xor(16)
// exchanges halves so every lane holds both children's 8 floats; lane l
// stores sum regs 0-3, lane l+16 stores regs 4-7 -> fully coalesced 512B row
// store. Stores evict-first (.cs): output is write-once.
static __device__ __forceinline__ void ldg256_el(const float* p, float* r) {
    asm volatile("ld.global.nc.L2::evict_last.v8.b32 "
                 "{%0,%1,%2,%3,%4,%5,%6,%7}, [%8];"
                 : "=f"(r[0]), "=f"(r[1]), "=f"(r[2]), "=f"(r[3]),
                   "=f"(r[4]), "=f"(r[5]), "=f"(r[6]), "=f"(r[7])
                 : "l"(p));
}

__global__ void __launch_bounds__(256)
prod_layer_kernel(const float* __restrict__ node_mars,
                  const float* __restrict__ element_mars,
                  const int* __restrict__ nids,
                  const int* __restrict__ cids,
                  float* __restrict__ out)
{
    const unsigned gwarp = (blockIdx.x * blockDim.x + threadIdx.x) >> 5;
    const unsigned lane  = threadIdx.x & 31;
    const unsigned base  = gwarp * NODES_PER_WARP;

    if (base >= NUM_LAYER_NODES) {
        if (base == NUM_LAYER_NODES) {
            // Reserved row 0: pass through element_mars[0, :] (d_out poisoned).
            const float4* src = reinterpret_cast<const float4*>(element_mars);
            float4* dst = reinterpret_cast<float4*>(out);
            dst[lane] = src[lane];
        }
        return;
    }

    const int4 n4  = __ldg(reinterpret_cast<const int4*>(&nids[base]));
    const int4 c01 = __ldg(reinterpret_cast<const int4*>(&cids[2 * base]));
    const int4 c23 = __ldg(reinterpret_cast<const int4*>(&cids[2 * base + 4]));

    const bool     hi    = lane >= 16;
    const unsigned chunk = (lane & 15) * 8;      // float offset of 32B chunk

    // Per-node child row selected by half-warp.
    const long long r0 = (long long)(hi ? c01.y : c01.x) * BATCH;
    const long long r1 = (long long)(hi ? c01.w : c01.z) * BATCH;
    const long long r2 = (long long)(hi ? c23.y : c23.x) * BATCH;
    const long long r3 = (long long)(hi ? c23.w : c23.z) * BATCH;

    // Issue all 4 x 256-bit gather loads up front (4KB outstanding/warp).
    float v0[8], v1[8], v2[8], v3[8];
    ldg256_el(node_mars + r0 + chunk, v0);
    ldg256_el(node_mars + r1 + chunk, v1);
    ldg256_el(node_mars + r2 + chunk, v2);
    ldg256_el(node_mars + r3 + chunk, v3);

    float4* o = reinterpret_cast<float4*>(out);
    // Store slot: lane l -> bytes [chunk*4, +16); lane l+16 -> [+16, +32).
    const unsigned f4slot = (lane & 15) * 2 + (hi ? 1 : 0);

    {
        float s[8];
        #pragma unroll
        for (int i = 0; i < 8; i++)
            s[i] = v0[i] + __shfl_xor_sync(0xffffffffu, v0[i], 16);
        float4 w = hi ? make_float4(s[4], s[5], s[6], s[7])
                      : make_float4(s[0], s[1], s[2], s[3]);
        __stcs(&o[(long long)n4.x * (BATCH / 4) + f4slot], w);
    }
    {
        float s[8];
        #pragma unroll
        for (int i = 0; i < 8; i++)
            s[i] = v1[i] + __shfl_xor_sync(0xffffffffu, v1[i], 16);
        float4 w = hi ? make_float4(s[4], s[5], s[6], s[7])
                      : make_float4(s[0], s[1], s[2], s[3]);
        __stcs(&o[(long long)n4.y * (BATCH / 4) + f4slot], w);
    }
    {
        float s[8];
        #pragma unroll
        for (int i = 0; i < 8; i++)
            s[i] = v2[i] + __shfl_xor_sync(0xffffffffu, v2[i], 16);
        float4 w = hi ? make_float4(s[4], s[5], s[6], s[7])
                      : make_float4(s[0], s[1], s[2], s[3]);
        __stcs(&o[(long long)n4.z * (BATCH / 4) + f4slot], w);
    }
    {
        float s[8];
        #pragma unroll
        for (int i = 0; i < 8; i++)
            s[i] = v3[i] + __shfl_xor_sync(0xffffffffu, v3[i], 16);
        float4 w = hi ? make_float4(s[4], s[5], s[6], s[7])
                      : make_float4(s[0], s[1], s[2], s[3]);
        __stcs(&o[(long long)n4.w * (BATCH / 4) + f4slot], w);
    }
}

extern "C" void kernel_launch(void* const* d_in, const int* in_sizes, int n_in,
                              void* d_out, int out_size)
{
    const float* node_mars    = (const float*)d_in[0];
    const float* element_mars = (const float*)d_in[1];
    const int*   nids         = (const int*)d_in[2];
    const int*   cids         = (const int*)d_in[3];
    float*       out          = (float*)d_out;

    const unsigned total_warps   = NUM_LAYER_NODES / NODES_PER_WARP + 1;
    const unsigned threads       = 256;               // 8 warps/block
    const unsigned warps_per_blk = threads / 32;
    const unsigned blocks = (total_warps + warps_per_blk - 1) / warps_per_blk;

    prod_layer_kernel<<<blocks, threads>>>(node_mars, element_mars, nids, cids, out);
}